// round 2
// baseline (speedup 1.0000x reference)
#include <cuda_runtime.h>

// Problem dims (fixed by the dataset): x [8,2048,4096] -> M=16384 rows, K=4096,
// weight [512,512,8] -> w_eff [N=4096, K=4096], bias [4096]. Output fp32 [M, N].
#define MDIM 16384
#define NDIM 4096
#define KDIM 4096

// Scratch for the expanded effective weight, row-major [N, K] (64 MB).
// __device__ global = module-load allocation, allowed by the harness rules.
__device__ float g_weff[(size_t)NDIM * KDIM];

// ---------------------------------------------------------------------------
// Kernel 1: expand octonion weight [512,512,8] into dense w_eff [4096,4096].
// w_eff[o*8+k][i*8+b] = sum_a mult[a,b,k] * w[o,i,a]; exactly one 'a'
// contributes per (k,b): a = KTAB[k][b] (index table is an involution),
// sign = STAB[a][b].
// ---------------------------------------------------------------------------
__global__ void build_weff_kernel(const float* __restrict__ w) {
    // Octonion multiplication: e_a * e_b = STAB[a][b] * e_{KTAB[a][b]}
    const signed char KTAB[64] = {
        0,1,2,3,4,5,6,7,
        1,0,3,2,5,4,7,6,
        2,3,0,1,6,7,4,5,
        3,2,1,0,7,6,5,4,
        4,5,6,7,0,1,2,3,
        5,4,7,6,1,0,3,2,
        6,7,4,5,2,3,0,1,
        7,6,5,4,3,2,1,0
    };
    const signed char STAB[64] = {
        +1,+1,+1,+1,+1,+1,+1,+1,
        +1,-1,+1,-1,+1,-1,-1,+1,
        +1,-1,-1,+1,+1,+1,-1,-1,
        +1,+1,-1,-1,+1,-1,+1,-1,
        +1,-1,-1,-1,-1,+1,+1,+1,
        +1,+1,-1,+1,-1,-1,-1,+1,
        +1,+1,+1,-1,-1,+1,-1,-1,
        +1,-1,+1,+1,-1,-1,+1,-1
    };

    int t = blockIdx.x * blockDim.x + threadIdx.x;   // 0 .. 512*512-1, one (o,i) pair
    if (t >= 512 * 512) return;
    int o = t >> 9;
    int i = t & 511;

    const float4* wp = reinterpret_cast<const float4*>(w + (size_t)t * 8);
    float4 wlo = wp[0];
    float4 whi = wp[1];
    float wv[8] = {wlo.x, wlo.y, wlo.z, wlo.w, whi.x, whi.y, whi.z, whi.w};

    #pragma unroll
    for (int k = 0; k < 8; ++k) {
        float out[8];
        #pragma unroll
        for (int b = 0; b < 8; ++b) {
            int a = KTAB[k * 8 + b];            // compile-time folded (full unroll)
            out[b] = (float)STAB[a * 8 + b] * wv[a];
        }
        float4* dst = reinterpret_cast<float4*>(
            g_weff + (size_t)(o * 8 + k) * KDIM + i * 8);
        dst[0] = make_float4(out[0], out[1], out[2], out[3]);
        dst[1] = make_float4(out[4], out[5], out[6], out[7]);
    }
}

// ---------------------------------------------------------------------------
// Kernel 2: SGEMM  C[M,N] = A[M,K] * w_eff[N,K]^T + bias[N]
// Both operands K-major => identical load paths. 128x128x16 tiles,
// 256 threads, 8x8 per thread, double-buffered SMEM.
// ---------------------------------------------------------------------------
__global__ __launch_bounds__(256, 2) void sgemm_kernel(
    const float* __restrict__ A,
    const float* __restrict__ bias,
    float* __restrict__ C)
{
    constexpr int BM = 128, BN = 128, BK = 16;
    __shared__ float As[2][BK][BM];
    __shared__ float Bs[2][BK][BN];

    const int tid = threadIdx.x;
    const int tx = tid & 15;         // output col group (8 cols)
    const int ty = tid >> 4;         // output row group (8 rows)
    const int rowBase = blockIdx.y * BM;
    const int colBase = blockIdx.x * BN;

    // Global-load mapping: 2048 floats per tile = 512 float4; 2 per thread.
    // float4 f handles tile row (f>>2), cols ((f&3)*4 .. +3). Second f = tid+256
    // -> same col group, row + 64.
    const int lr = tid >> 2;              // 0..63
    const int lc = (tid & 3) * 4;         // 0,4,8,12

    const float* Aptr = A + (size_t)(rowBase + lr) * KDIM + lc;
    const float* Bptr = g_weff + (size_t)(colBase + lr) * KDIM + lc;

    float acc[8][8];
    #pragma unroll
    for (int i = 0; i < 8; ++i)
        #pragma unroll
        for (int j = 0; j < 8; ++j) acc[i][j] = 0.0f;

    float4 pa0, pa1, pb0, pb1;

    // Prologue: load tile 0
    pa0 = *reinterpret_cast<const float4*>(Aptr);
    pa1 = *reinterpret_cast<const float4*>(Aptr + (size_t)64 * KDIM);
    pb0 = *reinterpret_cast<const float4*>(Bptr);
    pb1 = *reinterpret_cast<const float4*>(Bptr + (size_t)64 * KDIM);

    // store tile 0 into buffer 0 (transposed: As[k][m])
    As[0][lc + 0][lr] = pa0.x;  As[0][lc + 1][lr] = pa0.y;
    As[0][lc + 2][lr] = pa0.z;  As[0][lc + 3][lr] = pa0.w;
    As[0][lc + 0][lr + 64] = pa1.x;  As[0][lc + 1][lr + 64] = pa1.y;
    As[0][lc + 2][lr + 64] = pa1.z;  As[0][lc + 3][lr + 64] = pa1.w;
    Bs[0][lc + 0][lr] = pb0.x;  Bs[0][lc + 1][lr] = pb0.y;
    Bs[0][lc + 2][lr] = pb0.z;  Bs[0][lc + 3][lr] = pb0.w;
    Bs[0][lc + 0][lr + 64] = pb1.x;  Bs[0][lc + 1][lr + 64] = pb1.y;
    Bs[0][lc + 2][lr + 64] = pb1.z;  Bs[0][lc + 3][lr + 64] = pb1.w;
    __syncthreads();

    const int nTiles = KDIM / BK;   // 256
    for (int t = 0; t < nTiles; ++t) {
        const int cur = t & 1;
        const int nxt = cur ^ 1;

        if (t + 1 < nTiles) {
            const float* ap = Aptr + (t + 1) * BK;
            const float* bp = Bptr + (t + 1) * BK;
            pa0 = *reinterpret_cast<const float4*>(ap);
            pa1 = *reinterpret_cast<const float4*>(ap + (size_t)64 * KDIM);
            pb0 = *reinterpret_cast<const float4*>(bp);
            pb1 = *reinterpret_cast<const float4*>(bp + (size_t)64 * KDIM);
        }

        // compute on current buffer
        #pragma unroll
        for (int kk = 0; kk < BK; ++kk) {
            float ra[8], rb[8];
            *reinterpret_cast<float4*>(&ra[0]) =
                *reinterpret_cast<const float4*>(&As[cur][kk][ty * 8]);
            *reinterpret_cast<float4*>(&ra[4]) =
                *reinterpret_cast<const float4*>(&As[cur][kk][ty * 8 + 4]);
            *reinterpret_cast<float4*>(&rb[0]) =
                *reinterpret_cast<const float4*>(&Bs[cur][kk][tx * 8]);
            *reinterpret_cast<float4*>(&rb[4]) =
                *reinterpret_cast<const float4*>(&Bs[cur][kk][tx * 8 + 4]);
            #pragma unroll
            for (int i = 0; i < 8; ++i)
                #pragma unroll
                for (int j = 0; j < 8; ++j)
                    acc[i][j] += ra[i] * rb[j];
        }

        if (t + 1 < nTiles) {
            As[nxt][lc + 0][lr] = pa0.x;  As[nxt][lc + 1][lr] = pa0.y;
            As[nxt][lc + 2][lr] = pa0.z;  As[nxt][lc + 3][lr] = pa0.w;
            As[nxt][lc + 0][lr + 64] = pa1.x;  As[nxt][lc + 1][lr + 64] = pa1.y;
            As[nxt][lc + 2][lr + 64] = pa1.z;  As[nxt][lc + 3][lr + 64] = pa1.w;
            Bs[nxt][lc + 0][lr] = pb0.x;  Bs[nxt][lc + 1][lr] = pb0.y;
            Bs[nxt][lc + 2][lr] = pb0.z;  Bs[nxt][lc + 3][lr] = pb0.w;
            Bs[nxt][lc + 0][lr + 64] = pb1.x;  Bs[nxt][lc + 1][lr + 64] = pb1.y;
            Bs[nxt][lc + 2][lr + 64] = pb1.z;  Bs[nxt][lc + 3][lr + 64] = pb1.w;
            __syncthreads();
        }
    }

    // Epilogue: add bias, store
    float bv[8];
    *reinterpret_cast<float4*>(&bv[0]) =
        *reinterpret_cast<const float4*>(bias + colBase + tx * 8);
    *reinterpret_cast<float4*>(&bv[4]) =
        *reinterpret_cast<const float4*>(bias + colBase + tx * 8 + 4);

    #pragma unroll
    for (int i = 0; i < 8; ++i) {
        const int row = rowBase + ty * 8 + i;
        float* cp = C + (size_t)row * NDIM + colBase + tx * 8;
        float4 o0 = make_float4(acc[i][0] + bv[0], acc[i][1] + bv[1],
                                acc[i][2] + bv[2], acc[i][3] + bv[3]);
        float4 o1 = make_float4(acc[i][4] + bv[4], acc[i][5] + bv[5],
                                acc[i][6] + bv[6], acc[i][7] + bv[7]);
        *reinterpret_cast<float4*>(cp) = o0;
        *reinterpret_cast<float4*>(cp + 4) = o1;
    }
}

extern "C" void kernel_launch(void* const* d_in, const int* in_sizes, int n_in,
                              void* d_out, int out_size) {
    const float* x    = (const float*)d_in[0];   // [8,2048,4096]
    const float* w    = (const float*)d_in[1];   // [512,512,8]
    const float* bias = (const float*)d_in[2];   // [4096]
    float* out = (float*)d_out;                  // [16384,4096]

    build_weff_kernel<<<(512 * 512 + 255) / 256, 256>>>(w);

    dim3 grid(NDIM / 128, MDIM / 128);           // (32, 128)
    sgemm_kernel<<<grid, 256>>>(x, bias, out);
}

// round 5
// speedup vs baseline: 2.7562x; 2.7562x over previous
#include <cuda_runtime.h>
#include <cstdint>

#define MDIM 16384
#define NDIM 4096
#define KDIM 4096

// Module-load scratch (allowed): expanded weight + tf32-rounded x.
__device__ float g_weff[(size_t)NDIM * KDIM];   // 64 MB, [N, K] row-major
__device__ float g_x[(size_t)MDIM * KDIM];      // 256 MB, [M, K] row-major

// ---------------------------------------------------------------------------
// helpers
// ---------------------------------------------------------------------------
__device__ __forceinline__ uint32_t smem_u32(const void* p) {
    uint32_t a;
    asm("{ .reg .u64 t; cvta.to.shared.u64 t, %1; cvt.u32.u64 %0, t; }" : "=r"(a) : "l"(p));
    return a;
}
__device__ __forceinline__ float to_tf32(float x) {
    uint32_t r;
    asm("cvt.rn.tf32.f32 %0, %1;" : "=r"(r) : "f"(x));
    return __uint_as_float(r);
}
__device__ __forceinline__ void cp16(uint32_t s, const void* g) {
    asm volatile("cp.async.cg.shared.global [%0], [%1], 16;" :: "r"(s), "l"(g) : "memory");
}
#define CP_COMMIT() asm volatile("cp.async.commit_group;" ::: "memory")

__device__ __forceinline__ void ldsm4(uint32_t* r, uint32_t addr) {
    asm volatile("ldmatrix.sync.aligned.m8n8.x4.shared.b16 {%0,%1,%2,%3}, [%4];"
        : "=r"(r[0]), "=r"(r[1]), "=r"(r[2]), "=r"(r[3]) : "r"(addr));
}
__device__ __forceinline__ void ldsm2(uint32_t* r, uint32_t addr) {
    asm volatile("ldmatrix.sync.aligned.m8n8.x2.shared.b16 {%0,%1}, [%2];"
        : "=r"(r[0]), "=r"(r[1]) : "r"(addr));
}
__device__ __forceinline__ void mma_tf32(float* d, const uint32_t* a, const uint32_t* b) {
    asm volatile(
        "mma.sync.aligned.m16n8k8.row.col.f32.tf32.tf32.f32 "
        "{%0,%1,%2,%3}, {%4,%5,%6,%7}, {%8,%9}, {%0,%1,%2,%3};"
        : "+f"(d[0]), "+f"(d[1]), "+f"(d[2]), "+f"(d[3])
        : "r"(a[0]), "r"(a[1]), "r"(a[2]), "r"(a[3]), "r"(b[0]), "r"(b[1]));
}

// ---------------------------------------------------------------------------
// Kernel 0: round x to nearest tf32 into g_x.
// ---------------------------------------------------------------------------
__global__ void round_x_kernel(const float* __restrict__ x) {
    size_t i = (size_t)blockIdx.x * blockDim.x + threadIdx.x;
    float4 v = reinterpret_cast<const float4*>(x)[i];
    v.x = to_tf32(v.x); v.y = to_tf32(v.y); v.z = to_tf32(v.z); v.w = to_tf32(v.w);
    reinterpret_cast<float4*>(g_x)[i] = v;
}

// ---------------------------------------------------------------------------
// Kernel 1: expand octonion weight [512,512,8] -> w_eff [4096,4096], tf32-rounded.
// ---------------------------------------------------------------------------
__global__ void build_weff_kernel(const float* __restrict__ w) {
    const signed char KTAB[64] = {
        0,1,2,3,4,5,6,7, 1,0,3,2,5,4,7,6, 2,3,0,1,6,7,4,5, 3,2,1,0,7,6,5,4,
        4,5,6,7,0,1,2,3, 5,4,7,6,1,0,3,2, 6,7,4,5,2,3,0,1, 7,6,5,4,3,2,1,0 };
    const signed char STAB[64] = {
        +1,+1,+1,+1,+1,+1,+1,+1, +1,-1,+1,-1,+1,-1,-1,+1, +1,-1,-1,+1,+1,+1,-1,-1,
        +1,+1,-1,-1,+1,-1,+1,-1, +1,-1,-1,-1,-1,+1,+1,+1, +1,+1,-1,+1,-1,-1,-1,+1,
        +1,+1,+1,-1,-1,+1,-1,-1, +1,-1,+1,+1,-1,-1,+1,-1 };

    int t = blockIdx.x * blockDim.x + threadIdx.x;
    if (t >= 512 * 512) return;
    int o = t >> 9, i = t & 511;

    const float4* wp = reinterpret_cast<const float4*>(w + (size_t)t * 8);
    float4 wlo = wp[0], whi = wp[1];
    float wv[8] = {wlo.x, wlo.y, wlo.z, wlo.w, whi.x, whi.y, whi.z, whi.w};

    #pragma unroll
    for (int k = 0; k < 8; ++k) {
        float out[8];
        #pragma unroll
        for (int b = 0; b < 8; ++b) {
            int a = KTAB[k * 8 + b];
            out[b] = to_tf32((float)STAB[a * 8 + b] * wv[a]);
        }
        float4* dst = reinterpret_cast<float4*>(g_weff + (size_t)(o * 8 + k) * KDIM + i * 8);
        dst[0] = make_float4(out[0], out[1], out[2], out[3]);
        dst[1] = make_float4(out[4], out[5], out[6], out[7]);
    }
}

// ---------------------------------------------------------------------------
// Kernel 2: tf32 mma.sync GEMM. C[M,N] = g_x[M,K] @ g_weff[N,K]^T + bias.
// CTA 128x128, BK=32 (8 chunks of 16B per 128B row, XOR-swizzled).
// 8 warps = 2(M) x 4(N); warp tile 64x32 = 4x4 m16n8k8 atoms.
// 4-stage cp.async pipeline.
// ---------------------------------------------------------------------------
#define BK 32
#define STAGES 4
#define A_BYTES (128 * BK * 4)              // 16384
#define STAGE_BYTES (2 * A_BYTES)           // 32768: [A | B]
#define GEMM_SMEM (STAGES * STAGE_BYTES)    // 131072
#define NTILES (KDIM / BK)                  // 128

__global__ __launch_bounds__(256, 1) void gemm_mma_kernel(
    const float* __restrict__ bias, float* __restrict__ C)
{
    extern __shared__ char smem[];
    const uint32_t sb = smem_u32(smem);
    const int tid  = threadIdx.x;
    const int lane = tid & 31;
    const int wid  = tid >> 5;
    const int rowBase = blockIdx.y * 128;    // M
    const int colBase = blockIdx.x * 128;    // N
    const int warpM = (wid >> 2) * 64;
    const int warpN = (wid & 3) * 32;

    // ---- global->shared load mapping: thread covers 4 A-chunks + 4 B-chunks ----
    const int lr  = tid >> 1;                // row 0..127
    const int lcp = (tid & 1) * 4;           // chunk base: 0 or 4
    const float* gA = g_x    + (size_t)(rowBase + lr) * KDIM + lcp * 4;
    const float* gB = g_weff + (size_t)(colBase + lr) * KDIM + lcp * 4;
    uint32_t sAo[4], sBo[4];
    #pragma unroll
    for (int j = 0; j < 4; ++j) {
        int ch = lcp + j;
        uint32_t sw = (uint32_t)((ch ^ (lr & 7)) << 4);
        sAo[j] = sb + lr * 128 + sw;
        sBo[j] = sb + A_BYTES + lr * 128 + sw;
    }

    // ---- ldmatrix address bases (swizzle XOR term is constant per thread) ----
    const int swz = lane & 7;
    uint32_t aBase[4], bBase[4];
    {
        int rA = warpM + (lane & 15);
        #pragma unroll
        for (int am = 0; am < 4; ++am) aBase[am] = sb + (uint32_t)((rA + am * 16) * 128);
        int rB = warpN + (lane & 7);
        #pragma unroll
        for (int an = 0; an < 4; ++an) bBase[an] = sb + A_BYTES + (uint32_t)((rB + an * 8) * 128);
    }
    const int laneAhi = lane >> 4;           // 0/1 -> chunk +0/+1
    const int laneBhi = (lane >> 3) & 1;

    float acc[4][4][4];
    #pragma unroll
    for (int am = 0; am < 4; ++am)
        #pragma unroll
        for (int an = 0; an < 4; ++an)
            #pragma unroll
            for (int e = 0; e < 4; ++e) acc[am][an][e] = 0.0f;

    // ---- prologue: prefetch STAGES-1 tiles ----
    #pragma unroll
    for (int t = 0; t < STAGES - 1; ++t) {
        uint32_t so = (uint32_t)(t * STAGE_BYTES);
        const float* a = gA + t * BK;
        const float* b = gB + t * BK;
        #pragma unroll
        for (int j = 0; j < 4; ++j) cp16(sAo[j] + so, a + j * 4);
        #pragma unroll
        for (int j = 0; j < 4; ++j) cp16(sBo[j] + so, b + j * 4);
        CP_COMMIT();
    }

    // ---- mainloop ----
    #pragma unroll 1
    for (int t = 0; t < NTILES; ++t) {
        asm volatile("cp.async.wait_group 2;" ::: "memory");
        __syncthreads();

        // issue tile t+3 (overwrites buffer read at t-1; safe after sync)
        if (t + STAGES - 1 < NTILES) {
            int tn = t + STAGES - 1;
            uint32_t so = (uint32_t)((tn & (STAGES - 1)) * STAGE_BYTES);
            const float* a = gA + tn * BK;
            const float* b = gB + tn * BK;
            #pragma unroll
            for (int j = 0; j < 4; ++j) cp16(sAo[j] + so, a + j * 4);
            #pragma unroll
            for (int j = 0; j < 4; ++j) cp16(sBo[j] + so, b + j * 4);
        }
        CP_COMMIT();

        // compute on stage t
        const uint32_t so = (uint32_t)((t & (STAGES - 1)) * STAGE_BYTES);
        #pragma unroll
        for (int ks = 0; ks < 4; ++ks) {
            uint32_t a_frag[4][4], b_frag[4][2];
            const uint32_t qa = (uint32_t)(((2 * ks + laneAhi) ^ swz) << 4);
            const uint32_t qb = (uint32_t)(((2 * ks + laneBhi) ^ swz) << 4);
            #pragma unroll
            for (int am = 0; am < 4; ++am) ldsm4(a_frag[am], aBase[am] + so + qa);
            #pragma unroll
            for (int an = 0; an < 4; ++an) ldsm2(b_frag[an], bBase[an] + so + qb);
            #pragma unroll
            for (int am = 0; am < 4; ++am)
                #pragma unroll
                for (int an = 0; an < 4; ++an)
                    mma_tf32(acc[am][an], a_frag[am], b_frag[an]);
        }
    }

    // ---- epilogue: bias + store (c0,c1 = row, cols 2c..2c+1; c2,c3 = row+8) ----
    float2 bv[4];
    #pragma unroll
    for (int an = 0; an < 4; ++an)
        bv[an] = *reinterpret_cast<const float2*>(
            bias + colBase + warpN + an * 8 + (lane & 3) * 2);

    #pragma unroll
    for (int am = 0; am < 4; ++am) {
        const int r0 = rowBase + warpM + am * 16 + (lane >> 2);
        #pragma unroll
        for (int an = 0; an < 4; ++an) {
            const int col = colBase + warpN + an * 8 + (lane & 3) * 2;
            float2 lo = make_float2(acc[am][an][0] + bv[an].x, acc[am][an][1] + bv[an].y);
            float2 hi = make_float2(acc[am][an][2] + bv[an].x, acc[am][an][3] + bv[an].y);
            *reinterpret_cast<float2*>(C + (size_t)r0 * NDIM + col) = lo;
            *reinterpret_cast<float2*>(C + (size_t)(r0 + 8) * NDIM + col) = hi;
        }
    }
}

extern "C" void kernel_launch(void* const* d_in, const int* in_sizes, int n_in,
                              void* d_out, int out_size) {
    const float* x    = (const float*)d_in[0];   // [8,2048,4096]
    const float* w    = (const float*)d_in[1];   // [512,512,8]
    const float* bias = (const float*)d_in[2];   // [4096]
    float* out = (float*)d_out;                  // [16384,4096] fp32

    cudaFuncSetAttribute(gemm_mma_kernel,
                         cudaFuncAttributeMaxDynamicSharedMemorySize, GEMM_SMEM);

    round_x_kernel<<<(int)(((size_t)MDIM * KDIM / 4) / 256), 256>>>(x);
    build_weff_kernel<<<(512 * 512 + 255) / 256, 256>>>(w);

    dim3 grid(NDIM / 128, MDIM / 128);           // (32, 128)
    gemm_mma_kernel<<<grid, 256, GEMM_SMEM>>>(bias, out);
}